// round 6
// baseline (speedup 1.0000x reference)
#include <cuda_runtime.h>
#include <cuda_bf16.h>
#include <stdint.h>

#define NC 256      // clusters
#define NP 128      // points per cluster
#define VS 32
#define VS3 (VS*VS*VS)

// scratch (allocation-free rule: __device__ globals)
__device__ float g_vox[NC * VS3];            // 32 MB
__device__ float g_c1 [NC * 16 * 4096];      // 64 MB  (conv1, linear, no bias/relu)

// ---- packed f32x2 helpers (Blackwell) ----
__device__ __forceinline__ void ffma2(unsigned long long& d, unsigned long long a, unsigned long long b) {
    asm("fma.rn.f32x2 %0, %1, %2, %0;" : "+l"(d) : "l"(a), "l"(b));
}
__device__ __forceinline__ unsigned long long pack2(float lo, float hi) {
    unsigned long long r; asm("mov.b64 %0, {%1, %2};" : "=l"(r) : "f"(lo), "f"(hi)); return r;
}
__device__ __forceinline__ float2 unpack2(unsigned long long v) {
    float2 r; asm("mov.b64 {%0, %1}, %2;" : "=f"(r.x), "=f"(r.y) : "l"(v)); return r;
}

// ---------------------------------------------------------------- K1: voxelize
// 512 threads: thread = (point p = tid&127, quadrant sub = tid>>7) splitting the
// (i,j) splat loops 2x2 -> 4x less serial work per thread.
__global__ void __launch_bounds__(512) vox_kernel(
    const float* __restrict__ data, const int* __restrict__ clusts,
    const int* __restrict__ mask)
{
    extern __shared__ float vsh[];           // VS3 floats
    const int c = blockIdx.x;
    const int tid = threadIdx.x;

    float4* v4 = reinterpret_cast<float4*>(vsh);
    #pragma unroll
    for (int i = tid; i < VS3/4; i += 512) v4[i] = make_float4(0.f,0.f,0.f,0.f);

    const int p   = tid & 127;
    const int sub = tid >> 7;                // 0..3
    const int idx = clusts[c*NP + p];
    const bool m = mask[c*NP + p] != 0;
    const float px = data[idx*5+0];
    const float py = data[idx*5+1];
    const float pz = data[idx*5+2];
    const float val = data[idx*5+4];

    const float BIG = 1e9f;
    float mn[3], mx[3];
    mn[0] = m ? px :  BIG; mn[1] = m ? py :  BIG; mn[2] = m ? pz :  BIG;
    mx[0] = m ? px : -BIG; mx[1] = m ? py : -BIG; mx[2] = m ? pz : -BIG;
    #pragma unroll
    for (int off = 16; off; off >>= 1) {
        #pragma unroll
        for (int a = 0; a < 3; a++) {
            mn[a] = fminf(mn[a], __shfl_xor_sync(0xffffffffu, mn[a], off));
            mx[a] = fmaxf(mx[a], __shfl_xor_sync(0xffffffffu, mx[a], off));
        }
    }
    __shared__ float wmn[16][3], wmx[16][3];
    __shared__ float smins[3], srng[3], sgs;
    if ((tid & 31) == 0) {
        #pragma unroll
        for (int a = 0; a < 3; a++) { wmn[tid>>5][a] = mn[a]; wmx[tid>>5][a] = mx[a]; }
    }
    __syncthreads();
    if (tid == 0) {
        float rmax = -BIG;
        #pragma unroll
        for (int a = 0; a < 3; a++) {
            float lo = BIG, hi = -BIG;
            #pragma unroll
            for (int w = 0; w < 16; w++) { lo = fminf(lo, wmn[w][a]); hi = fmaxf(hi, wmx[w][a]); }
            smins[a] = lo;
            srng[a]  = hi - lo;
            rmax = fmaxf(rmax, hi - lo);
        }
        sgs = 1.0f / (rmax + 1.0f);
    }
    __syncthreads();

    if (m) {
        const float gs = sgs;
        const float ns = 1.0f / 32.0f;
        float v[3];
        v[0] = (px - smins[0] - srng[0]*0.5f - 0.5f) * gs + 0.5f;
        v[1] = (py - smins[1] - srng[1]*0.5f - 0.5f) * gs + 0.5f;
        v[2] = (pz - smins[2] - srng[2]*0.5f - 0.5f) * gs + 0.5f;
        int i0[3], i1[3];
        #pragma unroll
        for (int a = 0; a < 3; a++) {
            i0[a] = max(0,  (int)floorf(v[a] * 32.0f));
            i1[a] = min(31, (int)floorf((v[a] + gs) * 32.0f));
        }
        for (int i = i0[0] + (sub & 1); i <= i1[0]; i += 2) {
            float lo = (float)i * ns;
            float ox = fmaxf(fminf(v[0]+gs, lo+ns) - fmaxf(v[0], lo), 0.f) / gs;
            for (int j = i0[1] + (sub >> 1); j <= i1[1]; j += 2) {
                lo = (float)j * ns;
                float oy  = fmaxf(fminf(v[1]+gs, lo+ns) - fmaxf(v[1], lo), 0.f) / gs;
                float pre = val * ox * oy;
                for (int k = i0[2]; k <= i1[2]; k++) {
                    lo = (float)k * ns;
                    float oz = fmaxf(fminf(v[2]+gs, lo+ns) - fmaxf(v[2], lo), 0.f) / gs;
                    atomicAdd(&vsh[(i*32 + j)*32 + k], pre * oz);
                }
            }
        }
    }
    __syncthreads();
    float4* g4 = reinterpret_cast<float4*>(g_vox + (size_t)c * VS3);
    #pragma unroll
    for (int i = tid; i < VS3/4; i += 512) g4[i] = v4[i];
}

// ---------------------------------------------------------------- K2: conv1 (linear)
__global__ void __launch_bounds__(512) conv1_kernel(const float* __restrict__ W1)
{
    extern __shared__ float sh[];
    float* vsh = sh;                    // 32*32*33
    float* w1s = sh + 32*32*33;         // 432
    const int c = blockIdx.x;
    const int tid = threadIdx.x;

    const float* gv = g_vox + (size_t)c * VS3;
    for (int i = tid; i < VS3; i += 512) {
        int w = i & 31, h = (i >> 5) & 31, d = i >> 10;
        vsh[(d*32 + h)*33 + w] = gv[i];
    }
    if (tid < 432) w1s[tid] = W1[tid];
    __syncthreads();

    const int od  = tid >> 5;
    const int oh  = (tid >> 1) & 15;
    const int owh = tid & 1;
    float* outp = g_c1 + (size_t)c * 16 * 4096;

    for (int ocg = 0; ocg < 4; ocg++) {
        float acc[4][8];
        #pragma unroll
        for (int o = 0; o < 4; o++)
            #pragma unroll
            for (int i = 0; i < 8; i++) acc[o][i] = 0.f;

        #pragma unroll
        for (int kd = 0; kd < 3; kd++) {
            int d = 2*od + kd;
            #pragma unroll
            for (int kh = 0; kh < 3; kh++) {
                int h = 2*oh + kh;
                bool valid = (d < 32) && (h < 32);
                float xv[17];
                #pragma unroll
                for (int t = 0; t < 17; t++) {
                    int wabs = owh*16 + t;
                    xv[t] = (valid && wabs < 32) ? vsh[(d*32 + h)*33 + wabs] : 0.f;
                }
                #pragma unroll
                for (int o = 0; o < 4; o++) {
                    int oc = ocg*4 + o;
                    #pragma unroll
                    for (int kw = 0; kw < 3; kw++) {
                        float wv = w1s[oc*27 + kd*9 + kh*3 + kw];
                        #pragma unroll
                        for (int i = 0; i < 8; i++)
                            acc[o][i] = fmaf(xv[2*i + kw], wv, acc[o][i]);
                    }
                }
            }
        }
        #pragma unroll
        for (int o = 0; o < 4; o++)
            #pragma unroll
            for (int i = 0; i < 8; i++)
                outp[(ocg*4 + o)*4096 + (od*16 + oh)*16 + owh*8 + i] = acc[o][i];
    }
}

// ---------------------------------------------------------------- K3: per-edge fused
// smem (floats):
//   xbuf: 4 ic * [257 rows][20]  = 20560   (row 256 per ic = permanent zero row;
//                                           cols 16..19 of every row stay zero)
//   ybuf: 32 oc * 512            = 16384
//   wbuf: up to 4*27*64          =  6912
#define XROWS 257
#define XSTR  20
#define XB 0
#define YB (4*XROWS*XSTR)
#define WB (YB + 16384)
#define K3_FLOATS (WB + 6912)
#define K3_SMEM (K3_FLOATS * 4)

__global__ void __launch_bounds__(512) edge_kernel(
    const int* __restrict__ eidx, int E, int cmax,
    const float* __restrict__ b1, const float* __restrict__ W2,
    const float* __restrict__ b2, const float* __restrict__ W3,
    const float* __restrict__ b3, const float* __restrict__ Wfc,
    const float* __restrict__ bfc, float* __restrict__ out)
{
    extern __shared__ float sh[];
    float* xbuf = sh + XB;
    float* ybuf = sh + YB;
    float* wbuf = sh + WB;
    float* zbuf = sh + XB;          // overlay (xbuf dead by then)
    float* pooled = sh + XB + 4096;

    const int e = blockIdx.x;
    const int tid = threadIdx.x;
    const int ei = min(max(eidx[e], 0), cmax);
    const int ej = min(max(eidx[E + e], 0), cmax);
    const float* ci = g_c1 + (size_t)ei * 16 * 4096;
    const float* cj = g_c1 + (size_t)ej * 16 * 4096;

    const int odh = tid >> 3;        // 0..63
    const int ocg = tid & 7;         // 0..7
    const int od2 = odh >> 3, oh2 = odh & 7;

    // Zero the ENTIRE xbuf region once: establishes the per-ic zero row (256)
    // AND the pad columns 16..19 of every row (staging only writes cols 0..15,
    // but the conv reads col 16 for the ow=7,kw=2 tap -> must be 0).
    for (int i = tid; i < 4*XROWS*XSTR; i += 512) xbuf[i] = 0.f;

    unsigned long long acc2[4][4];   // [o][ow-pair]
    #pragma unroll
    for (int o = 0; o < 4; o++)
        #pragma unroll
        for (int pp = 0; pp < 4; pp++) acc2[o][pp] = 0ull;

    for (int icg = 0; icg < 4; icg++) {
        // stage x = relu(c1[i]+c1[j]+b1), rows padded to 20 (cols 16..19 remain 0)
        #pragma unroll
        for (int r = 0; r < 8; r++) {
            int fi  = tid + r*512;
            int icl = fi >> 10;
            int s   = (fi & 1023) * 4;
            const float4 a = *reinterpret_cast<const float4*>(ci + (icg*4 + icl)*4096 + s);
            const float4 b = *reinterpret_cast<const float4*>(cj + (icg*4 + icl)*4096 + s);
            const float bb = b1[icg*4 + icl];
            int row = s >> 4, w = s & 15;    // row = d*16+h
            float4 v;
            v.x = fmaxf(a.x + b.x + bb, 0.f);
            v.y = fmaxf(a.y + b.y + bb, 0.f);
            v.z = fmaxf(a.z + b.z + bb, 0.f);
            v.w = fmaxf(a.w + b.w + bb, 0.f);
            *reinterpret_cast<float4*>(&xbuf[(icl*XROWS + row)*XSTR + w]) = v;
        }
        // stage W2 chunk, layout [icl*27+k][ocg*4+o], oc = o*8+ocg
        for (int i = tid; i < 4*27*32; i += 512) {
            int o = i & 3, og = (i>>2)&7, rest = i >> 5;
            int k = rest % 27, icl = rest / 27;
            wbuf[i] = W2[(o*8 + og)*432 + (icg*4 + icl)*27 + k];
        }
        __syncthreads();

        #pragma unroll
        for (int icl = 0; icl < 4; icl++) {
            #pragma unroll
            for (int kd = 0; kd < 3; kd++) {
                int d = 2*od2 + kd;
                #pragma unroll
                for (int kh = 0; kh < 3; kh++) {
                    int h = 2*oh2 + kh;
                    int row = (d < 16 && h < 16) ? (d*16 + h) : 256;
                    const float* rp = &xbuf[(icl*XROWS + row)*XSTR];
                    float4 a0 = *reinterpret_cast<const float4*>(rp);
                    float4 a1 = *reinterpret_cast<const float4*>(rp + 4);
                    float4 a2 = *reinterpret_cast<const float4*>(rp + 8);
                    float4 a3 = *reinterpret_cast<const float4*>(rp + 12);
                    float x16 = rp[16];
                    float xr[17] = {a0.x,a0.y,a0.z,a0.w, a1.x,a1.y,a1.z,a1.w,
                                    a2.x,a2.y,a2.z,a2.w, a3.x,a3.y,a3.z,a3.w, x16};
                    unsigned long long xp[3][4];
                    #pragma unroll
                    for (int kw = 0; kw < 3; kw++)
                        #pragma unroll
                        for (int pp = 0; pp < 4; pp++)
                            xp[kw][pp] = pack2(xr[4*pp + kw], xr[4*pp + 2 + kw]);
                    #pragma unroll
                    for (int kw = 0; kw < 3; kw++) {
                        const float4 wv = *reinterpret_cast<const float4*>(
                            &wbuf[(icl*27 + kd*9 + kh*3 + kw)*32 + ocg*4]);
                        unsigned long long w0 = pack2(wv.x, wv.x);
                        unsigned long long w1 = pack2(wv.y, wv.y);
                        unsigned long long w2 = pack2(wv.z, wv.z);
                        unsigned long long w3 = pack2(wv.w, wv.w);
                        #pragma unroll
                        for (int pp = 0; pp < 4; pp++) {
                            ffma2(acc2[0][pp], xp[kw][pp], w0);
                            ffma2(acc2[1][pp], xp[kw][pp], w1);
                            ffma2(acc2[2][pp], xp[kw][pp], w2);
                            ffma2(acc2[3][pp], xp[kw][pp], w3);
                        }
                    }
                }
            }
        }
        __syncthreads();
    }

    // y = relu(acc + b2)
    #pragma unroll
    for (int o = 0; o < 4; o++) {
        int oc = o*8 + ocg;
        float bb = b2[oc];
        #pragma unroll
        for (int pp = 0; pp < 4; pp++) {
            float2 v = unpack2(acc2[o][pp]);
            ybuf[oc*512 + odh*8 + 2*pp + 0] = fmaxf(v.x + bb, 0.f);
            ybuf[oc*512 + odh*8 + 2*pp + 1] = fmaxf(v.y + bb, 0.f);
        }
    }
    __syncthreads();

    // conv3: thread = (sp = tid>>3, ocg = tid&7), 8 oc each (pairs via ulonglong2 weights)
    const int sp  = odh;             // 0..63
    const int od3 = sp >> 4, oh3 = (sp >> 2) & 3, ow3 = sp & 3;
    unsigned long long acc3[4] = {0ull, 0ull, 0ull, 0ull};

    for (int icg = 0; icg < 8; icg++) {
        // stage W3 chunk, layout [icl*27+k][ocg*8+o], oc = o*8+ocg
        for (int i = tid; i < 4*27*64; i += 512) {
            int o = i & 7, og = (i>>3)&7, rest = i >> 6;
            int k = rest % 27, icl = rest / 27;
            wbuf[i] = W3[(o*8 + og)*864 + (icg*4 + icl)*27 + k];
        }
        __syncthreads();
        #pragma unroll
        for (int icl = 0; icl < 4; icl++) {
            const float* yb = &ybuf[(icg*4 + icl)*512];
            int kk = 0;
            #pragma unroll
            for (int kd = 0; kd < 3; kd++) {
                int d = 2*od3 + kd;
                #pragma unroll
                for (int kh = 0; kh < 3; kh++) {
                    int h = 2*oh3 + kh;
                    #pragma unroll
                    for (int kw = 0; kw < 3; kw++, kk++) {
                        int w = 2*ow3 + kw;
                        float yv = (d < 8 && h < 8 && w < 8) ? yb[d*64 + h*8 + w] : 0.f;
                        unsigned long long yd = pack2(yv, yv);
                        const ulonglong2* wp = reinterpret_cast<const ulonglong2*>(
                            &wbuf[(icl*27 + kk)*64 + ocg*8]);
                        ulonglong2 wa = wp[0];
                        ulonglong2 wb = wp[1];
                        ffma2(acc3[0], yd, wa.x);
                        ffma2(acc3[1], yd, wa.y);
                        ffma2(acc3[2], yd, wb.x);
                        ffma2(acc3[3], yd, wb.y);
                    }
                }
            }
        }
        __syncthreads();
    }

    // z = relu(acc3 + b3) -> zbuf
    #pragma unroll
    for (int pr = 0; pr < 4; pr++) {
        float2 v = unpack2(acc3[pr]);
        int oc0 = (2*pr + 0)*8 + ocg;
        int oc1 = (2*pr + 1)*8 + ocg;
        zbuf[oc0*64 + sp] = fmaxf(v.x + b3[oc0], 0.f);
        zbuf[oc1*64 + sp] = fmaxf(v.y + b3[oc1], 0.f);
    }
    __syncthreads();

    if (tid < 64) {
        float s = 0.f;
        #pragma unroll 8
        for (int q = 0; q < 64; q++) s += zbuf[tid*64 + q];
        pooled[tid] = s * (1.f/64.f);
    }
    __syncthreads();
    if (tid < 64) {
        float a = bfc[tid];
        #pragma unroll 8
        for (int ic = 0; ic < 64; ic++)
            a = fmaf(pooled[ic], Wfc[ic*64 + tid], a);
        out[e*64 + tid] = a;
    }
}

// ---------------------------------------------------------------- launch
extern "C" void kernel_launch(void* const* d_in, const int* in_sizes, int n_in,
                              void* d_out, int out_size)
{
    const float* data   = (const float*)d_in[0];
    const int*   clusts = (const int*)d_in[1];
    const int*   cmask  = (const int*)d_in[2];
    const int*   eidx   = (const int*)d_in[3];
    const float* W1  = (const float*)d_in[4];
    const float* b1  = (const float*)d_in[5];
    const float* W2  = (const float*)d_in[6];
    const float* b2  = (const float*)d_in[7];
    const float* W3  = (const float*)d_in[8];
    const float* b3  = (const float*)d_in[9];
    const float* Wfc = (const float*)d_in[10];
    const float* bfc = (const float*)d_in[11];
    float* out = (float*)d_out;

    const int C = in_sizes[1] / NP;       // 256
    const int E = in_sizes[3] / 2;        // 1024

    cudaFuncSetAttribute(vox_kernel,   cudaFuncAttributeMaxDynamicSharedMemorySize, VS3*4);
    cudaFuncSetAttribute(conv1_kernel, cudaFuncAttributeMaxDynamicSharedMemorySize, (32*32*33 + 432)*4);
    cudaFuncSetAttribute(edge_kernel,  cudaFuncAttributeMaxDynamicSharedMemorySize, K3_SMEM);

    vox_kernel  <<<C, 512, VS3*4>>>(data, clusts, cmask);
    conv1_kernel<<<C, 512, (32*32*33 + 432)*4>>>(W1);
    edge_kernel <<<E, 512, K3_SMEM>>>(eidx, E, C - 1, b1, W2, b2, W3, b3, Wfc, bfc, out);
}

// round 7
// speedup vs baseline: 1.0505x; 1.0505x over previous
#include <cuda_runtime.h>
#include <cuda_bf16.h>
#include <stdint.h>

#define NC 256      // clusters
#define NP 128      // points per cluster
#define VS 32
#define VS3 (VS*VS*VS)

// scratch (allocation-free rule: __device__ globals)
__device__ float g_vox[NC * VS3];            // 32 MB
__device__ float g_c1 [NC * 16 * 4096];      // 64 MB  (conv1, linear, no bias/relu)

// ---------------------------------------------------------------- K1: voxelize
// 512 threads: thread = (point p = tid&127, quadrant sub = tid>>7) splitting the
// (i,j) splat loops 2x2 -> 4x less serial work per thread.
__global__ void __launch_bounds__(512) vox_kernel(
    const float* __restrict__ data, const int* __restrict__ clusts,
    const int* __restrict__ mask)
{
    extern __shared__ float vsh[];           // VS3 floats
    const int c = blockIdx.x;
    const int tid = threadIdx.x;

    float4* v4 = reinterpret_cast<float4*>(vsh);
    #pragma unroll
    for (int i = tid; i < VS3/4; i += 512) v4[i] = make_float4(0.f,0.f,0.f,0.f);

    const int p   = tid & 127;
    const int sub = tid >> 7;                // 0..3
    const int idx = clusts[c*NP + p];
    const bool m = mask[c*NP + p] != 0;
    const float px = data[idx*5+0];
    const float py = data[idx*5+1];
    const float pz = data[idx*5+2];
    const float val = data[idx*5+4];

    const float BIG = 1e9f;
    float mn[3], mx[3];
    mn[0] = m ? px :  BIG; mn[1] = m ? py :  BIG; mn[2] = m ? pz :  BIG;
    mx[0] = m ? px : -BIG; mx[1] = m ? py : -BIG; mx[2] = m ? pz : -BIG;
    #pragma unroll
    for (int off = 16; off; off >>= 1) {
        #pragma unroll
        for (int a = 0; a < 3; a++) {
            mn[a] = fminf(mn[a], __shfl_xor_sync(0xffffffffu, mn[a], off));
            mx[a] = fmaxf(mx[a], __shfl_xor_sync(0xffffffffu, mx[a], off));
        }
    }
    __shared__ float wmn[16][3], wmx[16][3];
    __shared__ float smins[3], srng[3], sgs;
    if ((tid & 31) == 0) {
        #pragma unroll
        for (int a = 0; a < 3; a++) { wmn[tid>>5][a] = mn[a]; wmx[tid>>5][a] = mx[a]; }
    }
    __syncthreads();
    if (tid == 0) {
        float rmax = -BIG;
        #pragma unroll
        for (int a = 0; a < 3; a++) {
            float lo = BIG, hi = -BIG;
            #pragma unroll
            for (int w = 0; w < 16; w++) { lo = fminf(lo, wmn[w][a]); hi = fmaxf(hi, wmx[w][a]); }
            smins[a] = lo;
            srng[a]  = hi - lo;
            rmax = fmaxf(rmax, hi - lo);
        }
        sgs = 1.0f / (rmax + 1.0f);
    }
    __syncthreads();

    if (m) {
        const float gs = sgs;
        const float ns = 1.0f / 32.0f;
        float v[3];
        v[0] = (px - smins[0] - srng[0]*0.5f - 0.5f) * gs + 0.5f;
        v[1] = (py - smins[1] - srng[1]*0.5f - 0.5f) * gs + 0.5f;
        v[2] = (pz - smins[2] - srng[2]*0.5f - 0.5f) * gs + 0.5f;
        int i0[3], i1[3];
        #pragma unroll
        for (int a = 0; a < 3; a++) {
            i0[a] = max(0,  (int)floorf(v[a] * 32.0f));
            i1[a] = min(31, (int)floorf((v[a] + gs) * 32.0f));
        }
        for (int i = i0[0] + (sub & 1); i <= i1[0]; i += 2) {
            float lo = (float)i * ns;
            float ox = fmaxf(fminf(v[0]+gs, lo+ns) - fmaxf(v[0], lo), 0.f) / gs;
            for (int j = i0[1] + (sub >> 1); j <= i1[1]; j += 2) {
                lo = (float)j * ns;
                float oy  = fmaxf(fminf(v[1]+gs, lo+ns) - fmaxf(v[1], lo), 0.f) / gs;
                float pre = val * ox * oy;
                for (int k = i0[2]; k <= i1[2]; k++) {
                    lo = (float)k * ns;
                    float oz = fmaxf(fminf(v[2]+gs, lo+ns) - fmaxf(v[2], lo), 0.f) / gs;
                    atomicAdd(&vsh[(i*32 + j)*32 + k], pre * oz);
                }
            }
        }
    }
    __syncthreads();
    float4* g4 = reinterpret_cast<float4*>(g_vox + (size_t)c * VS3);
    #pragma unroll
    for (int i = tid; i < VS3/4; i += 512) g4[i] = v4[i];
}

// ---------------------------------------------------------------- K2: conv1 (linear)
__global__ void __launch_bounds__(512) conv1_kernel(const float* __restrict__ W1)
{
    extern __shared__ float sh[];
    float* vsh = sh;                    // 32*32*33
    float* w1s = sh + 32*32*33;         // 432
    const int c = blockIdx.x;
    const int tid = threadIdx.x;

    const float* gv = g_vox + (size_t)c * VS3;
    for (int i = tid; i < VS3; i += 512) {
        int w = i & 31, h = (i >> 5) & 31, d = i >> 10;
        vsh[(d*32 + h)*33 + w] = gv[i];
    }
    if (tid < 432) w1s[tid] = W1[tid];
    __syncthreads();

    const int od  = tid >> 5;
    const int oh  = (tid >> 1) & 15;
    const int owh = tid & 1;
    float* outp = g_c1 + (size_t)c * 16 * 4096;

    for (int ocg = 0; ocg < 4; ocg++) {
        float acc[4][8];
        #pragma unroll
        for (int o = 0; o < 4; o++)
            #pragma unroll
            for (int i = 0; i < 8; i++) acc[o][i] = 0.f;

        #pragma unroll
        for (int kd = 0; kd < 3; kd++) {
            int d = 2*od + kd;
            #pragma unroll
            for (int kh = 0; kh < 3; kh++) {
                int h = 2*oh + kh;
                bool valid = (d < 32) && (h < 32);
                float xv[17];
                #pragma unroll
                for (int t = 0; t < 17; t++) {
                    int wabs = owh*16 + t;
                    xv[t] = (valid && wabs < 32) ? vsh[(d*32 + h)*33 + wabs] : 0.f;
                }
                #pragma unroll
                for (int o = 0; o < 4; o++) {
                    int oc = ocg*4 + o;
                    #pragma unroll
                    for (int kw = 0; kw < 3; kw++) {
                        float wv = w1s[oc*27 + kd*9 + kh*3 + kw];
                        #pragma unroll
                        for (int i = 0; i < 8; i++)
                            acc[o][i] = fmaf(xv[2*i + kw], wv, acc[o][i]);
                    }
                }
            }
        }
        #pragma unroll
        for (int o = 0; o < 4; o++)
            #pragma unroll
            for (int i = 0; i < 8; i++)
                outp[(ocg*4 + o)*4096 + (od*16 + oh)*16 + owh*8 + i] = acc[o][i];
    }
}

// ---------------------------------------------------------------- K3: per-edge fused
// smem (floats):
//   xbuf: 4 ic * [257 rows][20]  = 20560   (row 256 per ic = permanent zero row;
//                                           cols 16..19 of every row stay zero)
//   ybuf: 32 oc * 512            = 16384
//   wbuf: up to 4*27*64          =  6912
#define XROWS 257
#define XSTR  20
#define XB 0
#define YB (4*XROWS*XSTR)
#define WB (YB + 16384)
#define K3_FLOATS (WB + 6912)
#define K3_SMEM (K3_FLOATS * 4)

__global__ void __launch_bounds__(512) edge_kernel(
    const int* __restrict__ eidx, int E, int cmax,
    const float* __restrict__ b1, const float* __restrict__ W2,
    const float* __restrict__ b2, const float* __restrict__ W3,
    const float* __restrict__ b3, const float* __restrict__ Wfc,
    const float* __restrict__ bfc, float* __restrict__ out)
{
    extern __shared__ float sh[];
    float* xbuf = sh + XB;
    float* ybuf = sh + YB;
    float* wbuf = sh + WB;
    float* zbuf = sh + XB;          // overlay (xbuf dead by then)
    float* pooled = sh + XB + 4096;

    const int e = blockIdx.x;
    const int tid = threadIdx.x;
    const int ei = min(max(eidx[e], 0), cmax);
    const int ej = min(max(eidx[E + e], 0), cmax);
    const float* ci = g_c1 + (size_t)ei * 16 * 4096;
    const float* cj = g_c1 + (size_t)ej * 16 * 4096;

    const int odh = tid >> 3;        // 0..63
    const int ocg = tid & 7;         // 0..7
    const int od2 = odh >> 3, oh2 = odh & 7;

    // Zero the ENTIRE xbuf region once (zero row 256 per ic + pad cols 16..19).
    for (int i = tid; i < 4*XROWS*XSTR; i += 512) xbuf[i] = 0.f;

    float acc[4][8];                 // [o][ow], oc = o*8 + ocg
    #pragma unroll
    for (int o = 0; o < 4; o++)
        #pragma unroll
        for (int w = 0; w < 8; w++) acc[o][w] = 0.f;

    for (int icg = 0; icg < 4; icg++) {
        // stage x = relu(c1[i]+c1[j]+b1), rows padded to 20 (cols 16..19 remain 0)
        #pragma unroll
        for (int r = 0; r < 8; r++) {
            int fi  = tid + r*512;
            int icl = fi >> 10;
            int s   = (fi & 1023) * 4;
            const float4 a = *reinterpret_cast<const float4*>(ci + (icg*4 + icl)*4096 + s);
            const float4 b = *reinterpret_cast<const float4*>(cj + (icg*4 + icl)*4096 + s);
            const float bb = b1[icg*4 + icl];
            int row = s >> 4, w = s & 15;    // row = d*16+h
            float4 v;
            v.x = fmaxf(a.x + b.x + bb, 0.f);
            v.y = fmaxf(a.y + b.y + bb, 0.f);
            v.z = fmaxf(a.z + b.z + bb, 0.f);
            v.w = fmaxf(a.w + b.w + bb, 0.f);
            *reinterpret_cast<float4*>(&xbuf[(icl*XROWS + row)*XSTR + w]) = v;
        }
        // stage W2 chunk, layout [icl*27+k][ocg*4+o], oc = o*8+ocg
        for (int i = tid; i < 4*27*32; i += 512) {
            int o = i & 3, og = (i>>2)&7, rest = i >> 5;
            int k = rest % 27, icl = rest / 27;
            wbuf[i] = W2[(o*8 + og)*432 + (icg*4 + icl)*27 + k];
        }
        __syncthreads();

        #pragma unroll
        for (int icl = 0; icl < 4; icl++) {
            #pragma unroll
            for (int kd = 0; kd < 3; kd++) {
                int d = 2*od2 + kd;
                #pragma unroll
                for (int kh = 0; kh < 3; kh++) {
                    int h = 2*oh2 + kh;
                    int row = (d < 16 && h < 16) ? (d*16 + h) : 256;
                    const float* rp = &xbuf[(icl*XROWS + row)*XSTR];
                    float4 a0 = *reinterpret_cast<const float4*>(rp);
                    float4 a1 = *reinterpret_cast<const float4*>(rp + 4);
                    float4 a2 = *reinterpret_cast<const float4*>(rp + 8);
                    float4 a3 = *reinterpret_cast<const float4*>(rp + 12);
                    float x16 = rp[16];
                    float xr[17] = {a0.x,a0.y,a0.z,a0.w, a1.x,a1.y,a1.z,a1.w,
                                    a2.x,a2.y,a2.z,a2.w, a3.x,a3.y,a3.z,a3.w, x16};
                    #pragma unroll
                    for (int kw = 0; kw < 3; kw++) {
                        const float4 wv = *reinterpret_cast<const float4*>(
                            &wbuf[(icl*27 + kd*9 + kh*3 + kw)*32 + ocg*4]);
                        #pragma unroll
                        for (int ow = 0; ow < 8; ow++) {
                            float xv = xr[2*ow + kw];
                            acc[0][ow] = fmaf(xv, wv.x, acc[0][ow]);
                            acc[1][ow] = fmaf(xv, wv.y, acc[1][ow]);
                            acc[2][ow] = fmaf(xv, wv.z, acc[2][ow]);
                            acc[3][ow] = fmaf(xv, wv.w, acc[3][ow]);
                        }
                    }
                }
            }
        }
        __syncthreads();
    }

    // y = relu(acc + b2)
    #pragma unroll
    for (int o = 0; o < 4; o++) {
        int oc = o*8 + ocg;
        float bb = b2[oc];
        #pragma unroll
        for (int ow = 0; ow < 8; ow++)
            ybuf[oc*512 + odh*8 + ow] = fmaxf(acc[o][ow] + bb, 0.f);
    }
    __syncthreads();

    // conv3: thread = (sp = tid>>3, ocg = tid&7), 8 oc each; float4 weight loads
    const int sp  = odh;             // 0..63
    const int od3 = sp >> 4, oh3 = (sp >> 2) & 3, ow3 = sp & 3;
    float acc3[8] = {0.f,0.f,0.f,0.f,0.f,0.f,0.f,0.f};

    for (int icg = 0; icg < 8; icg++) {
        // stage W3 chunk, layout [icl*27+k][ocg*8+o], oc = o*8+ocg
        for (int i = tid; i < 4*27*64; i += 512) {
            int o = i & 7, og = (i>>3)&7, rest = i >> 6;
            int k = rest % 27, icl = rest / 27;
            wbuf[i] = W3[(o*8 + og)*864 + (icg*4 + icl)*27 + k];
        }
        __syncthreads();
        #pragma unroll
        for (int icl = 0; icl < 4; icl++) {
            const float* yb = &ybuf[(icg*4 + icl)*512];
            // hoist y taps into registers (guards fold to predicated selects)
            float yv[27];
            #pragma unroll
            for (int kd = 0; kd < 3; kd++) {
                int d = 2*od3 + kd;
                #pragma unroll
                for (int kh = 0; kh < 3; kh++) {
                    int h = 2*oh3 + kh;
                    #pragma unroll
                    for (int kw = 0; kw < 3; kw++) {
                        int w = 2*ow3 + kw;
                        yv[kd*9 + kh*3 + kw] =
                            (d < 8 && h < 8 && w < 8) ? yb[d*64 + h*8 + w] : 0.f;
                    }
                }
            }
            #pragma unroll
            for (int k = 0; k < 27; k++) {
                const float* wrow = &wbuf[(icl*27 + k)*64 + ocg*8];
                float4 wa = *reinterpret_cast<const float4*>(wrow);
                float4 wb = *reinterpret_cast<const float4*>(wrow + 4);
                float yk = yv[k];
                acc3[0] = fmaf(yk, wa.x, acc3[0]);
                acc3[1] = fmaf(yk, wa.y, acc3[1]);
                acc3[2] = fmaf(yk, wa.z, acc3[2]);
                acc3[3] = fmaf(yk, wa.w, acc3[3]);
                acc3[4] = fmaf(yk, wb.x, acc3[4]);
                acc3[5] = fmaf(yk, wb.y, acc3[5]);
                acc3[6] = fmaf(yk, wb.z, acc3[6]);
                acc3[7] = fmaf(yk, wb.w, acc3[7]);
            }
        }
        __syncthreads();
    }

    // z = relu(acc3 + b3) -> zbuf (overlay on xbuf region)
    #pragma unroll
    for (int o = 0; o < 8; o++) {
        int oc = o*8 + ocg;
        zbuf[oc*64 + sp] = fmaxf(acc3[o] + b3[oc], 0.f);
    }
    __syncthreads();

    if (tid < 64) {
        float s = 0.f;
        #pragma unroll 8
        for (int q = 0; q < 64; q++) s += zbuf[tid*64 + q];
        pooled[tid] = s * (1.f/64.f);
    }
    __syncthreads();
    if (tid < 64) {
        float a = bfc[tid];
        #pragma unroll 8
        for (int ic = 0; ic < 64; ic++)
            a = fmaf(pooled[ic], Wfc[ic*64 + tid], a);
        out[e*64 + tid] = a;
    }
}

// ---------------------------------------------------------------- launch
extern "C" void kernel_launch(void* const* d_in, const int* in_sizes, int n_in,
                              void* d_out, int out_size)
{
    const float* data   = (const float*)d_in[0];
    const int*   clusts = (const int*)d_in[1];
    const int*   cmask  = (const int*)d_in[2];
    const int*   eidx   = (const int*)d_in[3];
    const float* W1  = (const float*)d_in[4];
    const float* b1  = (const float*)d_in[5];
    const float* W2  = (const float*)d_in[6];
    const float* b2  = (const float*)d_in[7];
    const float* W3  = (const float*)d_in[8];
    const float* b3  = (const float*)d_in[9];
    const float* Wfc = (const float*)d_in[10];
    const float* bfc = (const float*)d_in[11];
    float* out = (float*)d_out;

    const int C = in_sizes[1] / NP;       // 256
    const int E = in_sizes[3] / 2;        // 1024

    cudaFuncSetAttribute(vox_kernel,   cudaFuncAttributeMaxDynamicSharedMemorySize, VS3*4);
    cudaFuncSetAttribute(conv1_kernel, cudaFuncAttributeMaxDynamicSharedMemorySize, (32*32*33 + 432)*4);
    cudaFuncSetAttribute(edge_kernel,  cudaFuncAttributeMaxDynamicSharedMemorySize, K3_SMEM);

    vox_kernel  <<<C, 512, VS3*4>>>(data, clusts, cmask);
    conv1_kernel<<<C, 512, (32*32*33 + 432)*4>>>(W1);
    edge_kernel <<<E, 512, K3_SMEM>>>(eidx, E, C - 1, b1, W2, b2, W3, b3, Wfc, bfc, out);
}

// round 8
// speedup vs baseline: 1.2356x; 1.1763x over previous
#include <cuda_runtime.h>
#include <cuda_bf16.h>
#include <stdint.h>

#define NC 256      // clusters
#define NP 128      // points per cluster
#define VS 32
#define VS3 (VS*VS*VS)

// scratch (allocation-free rule: __device__ globals)
__device__ float g_c1 [NC * 16 * 4096];      // 64 MB (conv1 output, linear, no bias/relu)
__device__ float g_W2t[4 * 3456];            // W2 permuted into smem staging order
__device__ float g_W3t[8 * 6912];            // W3 permuted into smem staging order

// ---------------------------------------------------------------- K0: weight permute
__global__ void wprep_kernel(const float* __restrict__ W2, const float* __restrict__ W3)
{
    int idx = blockIdx.x * blockDim.x + threadIdx.x;
    if (idx < 4*3456) {
        int icg = idx / 3456, r = idx % 3456;
        int row = r >> 5, c = r & 31;
        int ocg = c >> 2, o = c & 3;
        int icl = row / 27, k = row % 27;
        g_W2t[idx] = W2[(o*8 + ocg)*432 + (icg*4 + icl)*27 + k];
    }
    if (idx < 8*6912) {
        int icg = idx / 6912, r = idx % 6912;
        int row = r >> 6, c = r & 63;
        int ocg = c >> 3, o = c & 7;
        int icl = row / 27, k = row % 27;
        g_W3t[idx] = W3[(o*8 + ocg)*864 + (icg*4 + icl)*27 + k];
    }
}

// ---------------------------------------------------------------- K1: voxelize + conv1 (fused)
// smem: vsh padded [32][32][33] (vox accumulates here directly) + W1 432 floats
#define K1_FLOATS (32*32*33 + 432)
__global__ void __launch_bounds__(512) voxconv1_kernel(
    const float* __restrict__ data, const int* __restrict__ clusts,
    const int* __restrict__ mask, const float* __restrict__ W1)
{
    extern __shared__ float vsh[];           // [32*32][33] then w1s
    float* w1s = vsh + 32*32*33;
    const int c = blockIdx.x;
    const int tid = threadIdx.x;

    float4* v4 = reinterpret_cast<float4*>(vsh);
    #pragma unroll
    for (int i = tid; i < (32*32*33)/4; i += 512) v4[i] = make_float4(0.f,0.f,0.f,0.f);
    if (tid < 432) w1s[tid] = W1[tid];

    const int p   = tid & 127;
    const int sub = tid >> 7;                // 0..3 quadrant of (i,j) splat space
    const int idx = clusts[c*NP + p];
    const bool m = mask[c*NP + p] != 0;
    const float px = data[idx*5+0];
    const float py = data[idx*5+1];
    const float pz = data[idx*5+2];
    const float val = data[idx*5+4];

    const float BIG = 1e9f;
    float mn[3], mx[3];
    mn[0] = m ? px :  BIG; mn[1] = m ? py :  BIG; mn[2] = m ? pz :  BIG;
    mx[0] = m ? px : -BIG; mx[1] = m ? py : -BIG; mx[2] = m ? pz : -BIG;
    #pragma unroll
    for (int off = 16; off; off >>= 1) {
        #pragma unroll
        for (int a = 0; a < 3; a++) {
            mn[a] = fminf(mn[a], __shfl_xor_sync(0xffffffffu, mn[a], off));
            mx[a] = fmaxf(mx[a], __shfl_xor_sync(0xffffffffu, mx[a], off));
        }
    }
    __shared__ float wmn[16][3], wmx[16][3];
    __shared__ float smins[3], srng[3], sgs;
    if ((tid & 31) == 0) {
        #pragma unroll
        for (int a = 0; a < 3; a++) { wmn[tid>>5][a] = mn[a]; wmx[tid>>5][a] = mx[a]; }
    }
    __syncthreads();
    if (tid == 0) {
        float rmax = -BIG;
        #pragma unroll
        for (int a = 0; a < 3; a++) {
            float lo = BIG, hi = -BIG;
            #pragma unroll
            for (int w = 0; w < 16; w++) { lo = fminf(lo, wmn[w][a]); hi = fmaxf(hi, wmx[w][a]); }
            smins[a] = lo;
            srng[a]  = hi - lo;
            rmax = fmaxf(rmax, hi - lo);
        }
        sgs = 1.0f / (rmax + 1.0f);
    }
    __syncthreads();

    if (m) {
        const float gs = sgs;
        const float ns = 1.0f / 32.0f;
        float v[3];
        v[0] = (px - smins[0] - srng[0]*0.5f - 0.5f) * gs + 0.5f;
        v[1] = (py - smins[1] - srng[1]*0.5f - 0.5f) * gs + 0.5f;
        v[2] = (pz - smins[2] - srng[2]*0.5f - 0.5f) * gs + 0.5f;
        int i0[3], i1[3];
        #pragma unroll
        for (int a = 0; a < 3; a++) {
            i0[a] = max(0,  (int)floorf(v[a] * 32.0f));
            i1[a] = min(31, (int)floorf((v[a] + gs) * 32.0f));
        }
        for (int i = i0[0] + (sub & 1); i <= i1[0]; i += 2) {
            float lo = (float)i * ns;
            float ox = fmaxf(fminf(v[0]+gs, lo+ns) - fmaxf(v[0], lo), 0.f) / gs;
            for (int j = i0[1] + (sub >> 1); j <= i1[1]; j += 2) {
                lo = (float)j * ns;
                float oy  = fmaxf(fminf(v[1]+gs, lo+ns) - fmaxf(v[1], lo), 0.f) / gs;
                float pre = val * ox * oy;
                for (int k = i0[2]; k <= i1[2]; k++) {
                    lo = (float)k * ns;
                    float oz = fmaxf(fminf(v[2]+gs, lo+ns) - fmaxf(v[2], lo), 0.f) / gs;
                    atomicAdd(&vsh[(i*32 + j)*33 + k], pre * oz);
                }
            }
        }
    }
    __syncthreads();

    // ---- conv1 phase (reads vsh directly) ----
    const int od  = tid >> 5;
    const int oh  = (tid >> 1) & 15;
    const int owh = tid & 1;
    float* outp = g_c1 + (size_t)c * 16 * 4096;

    for (int ocg = 0; ocg < 4; ocg++) {
        float acc[4][8];
        #pragma unroll
        for (int o = 0; o < 4; o++)
            #pragma unroll
            for (int i = 0; i < 8; i++) acc[o][i] = 0.f;

        #pragma unroll
        for (int kd = 0; kd < 3; kd++) {
            int d = 2*od + kd;
            #pragma unroll
            for (int kh = 0; kh < 3; kh++) {
                int h = 2*oh + kh;
                bool valid = (d < 32) && (h < 32);
                float xv[17];
                #pragma unroll
                for (int t = 0; t < 17; t++) {
                    int wabs = owh*16 + t;
                    xv[t] = (valid && wabs < 32) ? vsh[(d*32 + h)*33 + wabs] : 0.f;
                }
                #pragma unroll
                for (int o = 0; o < 4; o++) {
                    int oc = ocg*4 + o;
                    #pragma unroll
                    for (int kw = 0; kw < 3; kw++) {
                        float wv = w1s[oc*27 + kd*9 + kh*3 + kw];
                        #pragma unroll
                        for (int i = 0; i < 8; i++)
                            acc[o][i] = fmaf(xv[2*i + kw], wv, acc[o][i]);
                    }
                }
            }
        }
        #pragma unroll
        for (int o = 0; o < 4; o++)
            #pragma unroll
            for (int i = 0; i < 8; i++)
                outp[(ocg*4 + o)*4096 + (od*16 + oh)*16 + owh*8 + i] = acc[o][i];
    }
}

// ---------------------------------------------------------------- K3: per-edge fused
#define XROWS 257
#define XSTR  20
#define XB 0
#define YB (4*XROWS*XSTR)
#define WB (YB + 16384)
#define K3_FLOATS (WB + 6912)
#define K3_SMEM (K3_FLOATS * 4)

// conv2 inner-unit macros: taps t = 2*ow + kw consumed directly from float4 components
#define FMA_OW(OW, T, W) \
    acc[0][OW] = fmaf(T, W.x, acc[0][OW]); \
    acc[1][OW] = fmaf(T, W.y, acc[1][OW]); \
    acc[2][OW] = fmaf(T, W.z, acc[2][OW]); \
    acc[3][OW] = fmaf(T, W.w, acc[3][OW]);
#define FMA_KW(W, T0,T1,T2,T3,T4,T5,T6,T7) \
    FMA_OW(0,T0,W) FMA_OW(1,T1,W) FMA_OW(2,T2,W) FMA_OW(3,T3,W) \
    FMA_OW(4,T4,W) FMA_OW(5,T5,W) FMA_OW(6,T6,W) FMA_OW(7,T7,W)

__global__ void __launch_bounds__(512) edge_kernel(
    const int* __restrict__ eidx, int E, int cmax,
    const float* __restrict__ b1,
    const float* __restrict__ b2,
    const float* __restrict__ b3, const float* __restrict__ Wfc,
    const float* __restrict__ bfc, float* __restrict__ out)
{
    extern __shared__ float sh[];
    float* xbuf = sh + XB;
    float* ybuf = sh + YB;
    float* wbuf = sh + WB;
    float* zbuf = sh + XB;          // overlay (xbuf dead by then)
    float* pooled = sh + XB + 4096;

    const int e = blockIdx.x;
    const int tid = threadIdx.x;
    const int ei = min(max(eidx[e], 0), cmax);
    const int ej = min(max(eidx[E + e], 0), cmax);
    const float* ci = g_c1 + (size_t)ei * 16 * 4096;
    const float* cj = g_c1 + (size_t)ej * 16 * 4096;

    const int odh = tid >> 3;        // 0..63
    const int ocg = tid & 7;         // 0..7
    const int od2 = odh >> 3, oh2 = odh & 7;

    // Zero xbuf once (zero row 256 per ic + pad cols 16..19 of every row).
    for (int i = tid; i < 4*XROWS*XSTR; i += 512) xbuf[i] = 0.f;

    float acc[4][8];                 // [o][ow], oc = o*8 + ocg
    #pragma unroll
    for (int o = 0; o < 4; o++)
        #pragma unroll
        for (int w = 0; w < 8; w++) acc[o][w] = 0.f;

    for (int icg = 0; icg < 4; icg++) {
        // stage x = relu(c1[i]+c1[j]+b1), rows padded to 20 (cols 16..19 remain 0)
        #pragma unroll
        for (int r = 0; r < 8; r++) {
            int fi  = tid + r*512;
            int icl = fi >> 10;
            int s   = (fi & 1023) * 4;
            const float4 a = *reinterpret_cast<const float4*>(ci + (icg*4 + icl)*4096 + s);
            const float4 b = *reinterpret_cast<const float4*>(cj + (icg*4 + icl)*4096 + s);
            const float bb = b1[icg*4 + icl];
            int row = s >> 4, w = s & 15;    // row = d*16+h
            float4 v;
            v.x = fmaxf(a.x + b.x + bb, 0.f);
            v.y = fmaxf(a.y + b.y + bb, 0.f);
            v.z = fmaxf(a.z + b.z + bb, 0.f);
            v.w = fmaxf(a.w + b.w + bb, 0.f);
            *reinterpret_cast<float4*>(&xbuf[(icl*XROWS + row)*XSTR + w]) = v;
        }
        // stage W2 chunk — coalesced float4 copy from pre-permuted g_W2t
        {
            const float4* src = reinterpret_cast<const float4*>(g_W2t + icg*3456);
            float4* dst = reinterpret_cast<float4*>(wbuf);
            for (int i = tid; i < 3456/4; i += 512) dst[i] = src[i];
        }
        __syncthreads();

        #pragma unroll
        for (int icl = 0; icl < 4; icl++) {
            #pragma unroll
            for (int kd = 0; kd < 3; kd++) {
                int d = 2*od2 + kd;
                #pragma unroll
                for (int kh = 0; kh < 3; kh++) {
                    int h = 2*oh2 + kh;
                    int row = (d < 16 && h < 16) ? (d*16 + h) : 256;
                    const float* rp = &xbuf[(icl*XROWS + row)*XSTR];
                    const float4 A0 = *reinterpret_cast<const float4*>(rp);
                    const float4 A1 = *reinterpret_cast<const float4*>(rp + 4);
                    const float4 A2 = *reinterpret_cast<const float4*>(rp + 8);
                    const float4 A3 = *reinterpret_cast<const float4*>(rp + 12);
                    const float X16 = rp[16];
                    const float* wk = &wbuf[(icl*27 + kd*9 + kh*3)*32 + ocg*4];
                    const float4 W0 = *reinterpret_cast<const float4*>(wk);
                    const float4 W1v = *reinterpret_cast<const float4*>(wk + 32);
                    const float4 W2v = *reinterpret_cast<const float4*>(wk + 64);
                    FMA_KW(W0,  A0.x,A0.z,A1.x,A1.z,A2.x,A2.z,A3.x,A3.z)
                    FMA_KW(W1v, A0.y,A0.w,A1.y,A1.w,A2.y,A2.w,A3.y,A3.w)
                    FMA_KW(W2v, A0.z,A1.x,A1.z,A2.x,A2.z,A3.x,A3.z,X16)
                }
            }
        }
        __syncthreads();
    }

    // y = relu(acc + b2)
    #pragma unroll
    for (int o = 0; o < 4; o++) {
        int oc = o*8 + ocg;
        float bb = b2[oc];
        #pragma unroll
        for (int ow = 0; ow < 8; ow++)
            ybuf[oc*512 + odh*8 + ow] = fmaxf(acc[o][ow] + bb, 0.f);
    }
    __syncthreads();

    // conv3: thread = (sp = tid>>3, ocg = tid&7), 8 oc each; float4 weight loads
    const int sp  = odh;             // 0..63
    const int od3 = sp >> 4, oh3 = (sp >> 2) & 3, ow3 = sp & 3;
    float acc3[8] = {0.f,0.f,0.f,0.f,0.f,0.f,0.f,0.f};

    for (int icg = 0; icg < 8; icg++) {
        // stage W3 chunk — coalesced float4 copy from pre-permuted g_W3t
        {
            const float4* src = reinterpret_cast<const float4*>(g_W3t + icg*6912);
            float4* dst = reinterpret_cast<float4*>(wbuf);
            for (int i = tid; i < 6912/4; i += 512) dst[i] = src[i];
        }
        __syncthreads();
        #pragma unroll
        for (int icl = 0; icl < 4; icl++) {
            const float* yb = &ybuf[(icg*4 + icl)*512];
            float yv[27];
            #pragma unroll
            for (int kd = 0; kd < 3; kd++) {
                int d = 2*od3 + kd;
                #pragma unroll
                for (int kh = 0; kh < 3; kh++) {
                    int h = 2*oh3 + kh;
                    #pragma unroll
                    for (int kw = 0; kw < 3; kw++) {
                        int w = 2*ow3 + kw;
                        yv[kd*9 + kh*3 + kw] =
                            (d < 8 && h < 8 && w < 8) ? yb[d*64 + h*8 + w] : 0.f;
                    }
                }
            }
            #pragma unroll
            for (int k = 0; k < 27; k++) {
                const float* wrow = &wbuf[(icl*27 + k)*64 + ocg*8];
                float4 wa = *reinterpret_cast<const float4*>(wrow);
                float4 wb = *reinterpret_cast<const float4*>(wrow + 4);
                float yk = yv[k];
                acc3[0] = fmaf(yk, wa.x, acc3[0]);
                acc3[1] = fmaf(yk, wa.y, acc3[1]);
                acc3[2] = fmaf(yk, wa.z, acc3[2]);
                acc3[3] = fmaf(yk, wa.w, acc3[3]);
                acc3[4] = fmaf(yk, wb.x, acc3[4]);
                acc3[5] = fmaf(yk, wb.y, acc3[5]);
                acc3[6] = fmaf(yk, wb.z, acc3[6]);
                acc3[7] = fmaf(yk, wb.w, acc3[7]);
            }
        }
        __syncthreads();
    }

    // z = relu(acc3 + b3) -> zbuf (overlay on xbuf region)
    #pragma unroll
    for (int o = 0; o < 8; o++) {
        int oc = o*8 + ocg;
        zbuf[oc*64 + sp] = fmaxf(acc3[o] + b3[oc], 0.f);
    }
    __syncthreads();

    if (tid < 64) {
        float s = 0.f;
        #pragma unroll 8
        for (int q = 0; q < 64; q++) s += zbuf[tid*64 + q];
        pooled[tid] = s * (1.f/64.f);
    }
    __syncthreads();
    if (tid < 64) {
        float a = bfc[tid];
        #pragma unroll 8
        for (int ic = 0; ic < 64; ic++)
            a = fmaf(pooled[ic], Wfc[ic*64 + tid], a);
        out[e*64 + tid] = a;
    }
}

// ---------------------------------------------------------------- launch
extern "C" void kernel_launch(void* const* d_in, const int* in_sizes, int n_in,
                              void* d_out, int out_size)
{
    const float* data   = (const float*)d_in[0];
    const int*   clusts = (const int*)d_in[1];
    const int*   cmask  = (const int*)d_in[2];
    const int*   eidx   = (const int*)d_in[3];
    const float* W1  = (const float*)d_in[4];
    const float* b1  = (const float*)d_in[5];
    const float* W2  = (const float*)d_in[6];
    const float* b2  = (const float*)d_in[7];
    const float* W3  = (const float*)d_in[8];
    const float* b3  = (const float*)d_in[9];
    const float* Wfc = (const float*)d_in[10];
    const float* bfc = (const float*)d_in[11];
    float* out = (float*)d_out;

    const int C = in_sizes[1] / NP;       // 256
    const int E = in_sizes[3] / 2;        // 1024

    cudaFuncSetAttribute(voxconv1_kernel, cudaFuncAttributeMaxDynamicSharedMemorySize, K1_FLOATS*4);
    cudaFuncSetAttribute(edge_kernel,     cudaFuncAttributeMaxDynamicSharedMemorySize, K3_SMEM);

    wprep_kernel   <<<(8*6912 + 511)/512, 512>>>(W2, W3);
    voxconv1_kernel<<<C, 512, K1_FLOATS*4>>>(data, clusts, cmask, W1);
    edge_kernel    <<<E, 512, K3_SMEM>>>(eidx, E, C - 1, b1, b2, b3, Wfc, bfc, out);
}